// round 1
// baseline (speedup 1.0000x reference)
#include <cuda_runtime.h>
#include <cuda_bf16.h>

#define T_LEN   16384
#define T_MASK  (T_LEN - 1)
#define EPS_F   1e-7f
#define BLK     256
#define MAX_BLOCKS 4096

__device__ float g_pnum[MAX_BLOCKS];
__device__ float g_pden[MAX_BLOCKS];

__device__ __forceinline__ float warp_sum(float v) {
#pragma unroll
    for (int o = 16; o; o >>= 1) v += __shfl_xor_sync(0xffffffffu, v, o);
    return v;
}

// log(sigmoid(x) + eps), fast-math
__device__ __forceinline__ float log_sig_eps(float x) {
    float e = __expf(-x);                 // EX2 path
    float s = __fdividef(1.0f, 1.0f + e); // RCP path
    return __logf(s + EPS_F);             // LG2 path
}

__global__ void __launch_bounds__(BLK)
reinforce_pass1(const float4* __restrict__ lp,
                const float4* __restrict__ lg,
                const float4* __restrict__ wt,
                int nvec)
{
    float num = 0.0f, den = 0.0f;
    const int stride = gridDim.x * blockDim.x;
    for (int v = blockIdx.x * blockDim.x + threadIdx.x; v < nvec; v += stride) {
        float4 a = lp[v];
        float4 b = lg[v];
        float4 c = wt[v];
        // t for element 0 of this vec; T_LEN divisible by 4 so no wrap within the quad
        float tb = (float)(((v << 2) & T_MASK) + 1);

        float r0 = log_sig_eps(b.x);
        float r1 = log_sig_eps(b.y);
        float r2 = log_sig_eps(b.z);
        float r3 = log_sig_eps(b.w);

        num = fmaf(c.x * c.x * r0 * a.x, tb,          num);
        num = fmaf(c.y * c.y * r1 * a.y, tb + 1.0f,   num);
        num = fmaf(c.z * c.z * r2 * a.z, tb + 2.0f,   num);
        num = fmaf(c.w * c.w * r3 * a.w, tb + 3.0f,   num);
        den += (c.x + c.y) + (c.z + c.w);
    }

    num = warp_sum(num);
    den = warp_sum(den);

    __shared__ float sn[BLK / 32], sd[BLK / 32];
    int wid = threadIdx.x >> 5, lid = threadIdx.x & 31;
    if (lid == 0) { sn[wid] = num; sd[wid] = den; }
    __syncthreads();
    if (threadIdx.x < BLK / 32) {
        num = sn[threadIdx.x];
        den = sd[threadIdx.x];
#pragma unroll
        for (int o = (BLK / 32) >> 1; o; o >>= 1) {
            num += __shfl_xor_sync(0xffu, num, o);
            den += __shfl_xor_sync(0xffu, den, o);
        }
        if (threadIdx.x == 0) { g_pnum[blockIdx.x] = num; g_pden[blockIdx.x] = den; }
    }
}

__global__ void __launch_bounds__(1024)
reinforce_pass2(float* __restrict__ out, int nblocks)
{
    float num = 0.0f, den = 0.0f;
    for (int i = threadIdx.x; i < nblocks; i += 1024) {
        num += g_pnum[i];
        den += g_pden[i];
    }
    num = warp_sum(num);
    den = warp_sum(den);

    __shared__ float sn[32], sd[32];
    int wid = threadIdx.x >> 5, lid = threadIdx.x & 31;
    if (lid == 0) { sn[wid] = num; sd[wid] = den; }
    __syncthreads();
    if (threadIdx.x < 32) {
        num = sn[threadIdx.x];
        den = sd[threadIdx.x];
        num = warp_sum(num);
        den = warp_sum(den);
        if (threadIdx.x == 0) out[0] = num / den;
    }
}

extern "C" void kernel_launch(void* const* d_in, const int* in_sizes, int n_in,
                              void* d_out, int out_size)
{
    const float4* lp = (const float4*)d_in[0];  // log_probs [B,T]
    const float4* lg = (const float4*)d_in[1];  // logits    [B,T,1]
    const float4* wt = (const float4*)d_in[2];  // weight    [B,T]
    float* out = (float*)d_out;

    int n = in_sizes[0];          // B*T = 8388608, divisible by 4
    int nvec = n >> 2;

    int blocks = 148 * 8;         // 1184 blocks @ 256 thr: full-chip, grid-stride
    if (blocks > MAX_BLOCKS) blocks = MAX_BLOCKS;

    reinforce_pass1<<<blocks, BLK>>>(lp, lg, wt, nvec);
    reinforce_pass2<<<1, 1024>>>(out, blocks);
}